// round 1
// baseline (speedup 1.0000x reference)
#include <cuda_runtime.h>
#include <stdint.h>

#define NMAX 50000
#define EMAX 1600000

// ---------------- scratch (device globals; no allocation) ----------------
__device__ float4 g_h4[NMAX * 16];      // h [N,64]
__device__ float4 g_asrc4[NMAX];        // a_src [N,4]
__device__ float4 g_adst4[NMAX];        // a_dst [N,4]
__device__ float  g_v[64];              // v [16,4]  (d*4+h)
__device__ float  g_vsum[4];
__device__ float4 g_alpha4[EMAX];       // per-edge logits -> exp values [E,4]
__device__ uint4  g_amax4[NMAX];        // encoded float max per (n,h)
__device__ float4 g_denom4[NMAX];       // softmax denominators [N,4]

__device__ __forceinline__ unsigned fenc(float f) {
    unsigned u = __float_as_uint(f);
    return (u & 0x80000000u) ? ~u : (u | 0x80000000u);
}
__device__ __forceinline__ float fdec(unsigned k) {
    return __uint_as_float((k & 0x80000000u) ? (k & 0x7fffffffu) : ~k);
}
__device__ __forceinline__ float lrelu(float a) { return a > 0.f ? a : 0.2f * a; }

// ---------------- K1: v[d,h] = sum_c W_edge[d,h*16+c]*att_edge[h,c] ------
__global__ void k_prep(const float* __restrict__ We, const float* __restrict__ ae) {
    int t = threadIdx.x;   // 64 threads
    int d = t >> 2, h = t & 3;
    float s = 0.f;
#pragma unroll
    for (int c = 0; c < 16; c++) s += We[d * 64 + h * 16 + c] * ae[h * 16 + c];
    g_v[t] = s;
    __syncthreads();
    if (t < 4) {
        float ss = 0.f;
#pragma unroll
        for (int dd = 0; dd < 16; dd++) ss += g_v[dd * 4 + t];
        g_vsum[t] = ss;
    }
}

// ---------------- K2: h = x @ W  (x:[N,128], W:[128,64]) -----------------
// block 256: 32 nodes/block, 8 threads/node, 8 channels/thread
__global__ void k_gemm(const float* __restrict__ x, const float* __restrict__ W, int N) {
    __shared__ __align__(16) float sW[128 * 64];
    for (int i = threadIdx.x; i < 128 * 64; i += 256) sW[i] = W[i];
    __syncthreads();
    int t = threadIdx.x;
    int n = blockIdx.x * 32 + (t >> 3);
    if (n >= N) return;
    int j0 = (t & 7) * 8;
    const float* xr = x + n * 128;
    float acc[8] = {0, 0, 0, 0, 0, 0, 0, 0};
#pragma unroll 4
    for (int i = 0; i < 128; i++) {
        float xv = __ldg(xr + i);
        const float4* wp = reinterpret_cast<const float4*>(sW + i * 64 + j0);
        float4 w0 = wp[0], w1 = wp[1];
        acc[0] += xv * w0.x; acc[1] += xv * w0.y; acc[2] += xv * w0.z; acc[3] += xv * w0.w;
        acc[4] += xv * w1.x; acc[5] += xv * w1.y; acc[6] += xv * w1.z; acc[7] += xv * w1.w;
    }
    float4* o4 = reinterpret_cast<float4*>((float*)g_h4 + n * 64 + j0);
    o4[0] = make_float4(acc[0], acc[1], acc[2], acc[3]);
    o4[1] = make_float4(acc[4], acc[5], acc[6], acc[7]);
}

// ---------------- K3: a_src/a_dst per (n,h) -------------------------------
__global__ void k_att_nodes(const float* __restrict__ att_src,
                            const float* __restrict__ att_dst, int N) {
    int t = blockIdx.x * blockDim.x + threadIdx.x;
    if (t >= N * 4) return;
    int n = t >> 2, h = t & 3;
    const float* hv = (const float*)g_h4 + n * 64 + h * 16;
    float s1 = 0.f, s2 = 0.f;
#pragma unroll
    for (int c = 0; c < 16; c++) {
        float v = hv[c];
        s1 += v * __ldg(att_src + h * 16 + c);
        s2 += v * __ldg(att_dst + h * 16 + c);
    }
    ((float*)g_asrc4)[t] = s1;
    ((float*)g_adst4)[t] = s2;
}

// ---------------- K4: init amax with self-loop logit; denom=0 -------------
__global__ void k_init(int N) {
    int t = blockIdx.x * blockDim.x + threadIdx.x;
    if (t >= N * 4) return;
    int h = t & 3;
    float a = ((const float*)g_asrc4)[t] + ((const float*)g_adst4)[t] + g_vsum[h];
    a = lrelu(a);
    ((unsigned*)g_amax4)[t] = fenc(a);
    ((float*)g_denom4)[t] = 0.f;
}

// ---------------- K5: per-edge logits + atomicMax into dst ----------------
__global__ void k_edge_alpha(const int* __restrict__ ei, const float4* __restrict__ ea4, int E) {
    __shared__ float sv[64];
    if (threadIdx.x < 64) sv[threadIdx.x] = g_v[threadIdx.x];
    __syncthreads();
    int e = blockIdx.x * blockDim.x + threadIdx.x;
    if (e >= E) return;
    int src = ei[e], dst = ei[E + e];
    float a0 = 0.f, a1 = 0.f, a2 = 0.f, a3 = 0.f;
#pragma unroll
    for (int k = 0; k < 4; k++) {
        float4 q = ea4[e * 4 + k];
        const float* vp = sv + k * 16;
        a0 += q.x * vp[0] + q.y * vp[4] + q.z * vp[8]  + q.w * vp[12];
        a1 += q.x * vp[1] + q.y * vp[5] + q.z * vp[9]  + q.w * vp[13];
        a2 += q.x * vp[2] + q.y * vp[6] + q.z * vp[10] + q.w * vp[14];
        a3 += q.x * vp[3] + q.y * vp[7] + q.z * vp[11] + q.w * vp[15];
    }
    float4 as = g_asrc4[src];
    float4 ad = g_adst4[dst];
    float4 o;
    o.x = lrelu(as.x + ad.x + a0);
    o.y = lrelu(as.y + ad.y + a1);
    o.z = lrelu(as.z + ad.z + a2);
    o.w = lrelu(as.w + ad.w + a3);
    g_alpha4[e] = o;
    unsigned* am = (unsigned*)(g_amax4 + dst);
    atomicMax(am + 0, fenc(o.x));
    atomicMax(am + 1, fenc(o.y));
    atomicMax(am + 2, fenc(o.z));
    atomicMax(am + 3, fenc(o.w));
}

// ---------------- K6: exp(alpha - max), accumulate denom ------------------
__global__ void k_edge_exp(const int* __restrict__ ei, int E) {
    int e = blockIdx.x * blockDim.x + threadIdx.x;
    if (e >= E) return;
    int dst = ei[E + e];
    float4 al = g_alpha4[e];
    uint4 mk = g_amax4[dst];
    float4 ex;
    ex.x = __expf(al.x - fdec(mk.x));
    ex.y = __expf(al.y - fdec(mk.y));
    ex.z = __expf(al.z - fdec(mk.z));
    ex.w = __expf(al.w - fdec(mk.w));
    g_alpha4[e] = ex;
    float* dn = (float*)(g_denom4 + dst);
    atomicAdd(dn + 0, ex.x);
    atomicAdd(dn + 1, ex.y);
    atomicAdd(dn + 2, ex.z);
    atomicAdd(dn + 3, ex.w);
}

// ---------------- K7: fold self-loop into denom, seed output --------------
__global__ void k_node_finalize(const float* __restrict__ bias, float* __restrict__ out, int N) {
    int n = blockIdx.x;
    int t = threadIdx.x;   // 64
    __shared__ float satt[4];
    if (t < 4) {
        float a = ((const float*)g_asrc4)[n * 4 + t] + ((const float*)g_adst4)[n * 4 + t] + g_vsum[t];
        a = lrelu(a);
        float mx = fdec(((const unsigned*)g_amax4)[n * 4 + t]);
        float exl = __expf(a - mx);
        float dn = ((const float*)g_denom4)[n * 4 + t] + exl;
        ((float*)g_denom4)[n * 4 + t] = dn;
        satt[t] = exl / dn;
    }
    __syncthreads();
    out[n * 64 + t] = satt[t >> 4] * ((const float*)g_h4)[n * 64 + t] + __ldg(bias + t);
}

// ---------------- K8: weighted scatter-add, one warp per edge -------------
__global__ void k_scatter(const int* __restrict__ ei, float* __restrict__ out, int E) {
    int e = blockIdx.x * 8 + (threadIdx.x >> 5);
    int lane = threadIdx.x & 31;
    if (e >= E) return;
    int src = ei[e], dst = ei[E + e];
    float w = 0.f;
    if (lane < 4) {
        float ex = ((const float*)g_alpha4)[e * 4 + lane];
        float dn = ((const float*)g_denom4)[dst * 4 + lane];
        w = ex * __frcp_rn(dn);
    }
    float w0 = __shfl_sync(0xffffffffu, w, lane >> 4);
    float w1 = __shfl_sync(0xffffffffu, w, 2 + (lane >> 4));
    const float* hs = (const float*)g_h4 + src * 64;
    atomicAdd(out + dst * 64 + lane,      w0 * hs[lane]);
    atomicAdd(out + dst * 64 + 32 + lane, w1 * hs[32 + lane]);
}

// ---------------- launch ---------------------------------------------------
extern "C" void kernel_launch(void* const* d_in, const int* in_sizes, int n_in,
                              void* d_out, int out_size) {
    const float* x        = (const float*)d_in[0];
    const int*   ei       = (const int*)d_in[1];
    const float* ea       = (const float*)d_in[2];
    const float* W        = (const float*)d_in[3];
    const float* att_src  = (const float*)d_in[4];
    const float* att_dst  = (const float*)d_in[5];
    const float* W_edge   = (const float*)d_in[6];
    const float* att_edge = (const float*)d_in[7];
    const float* bias     = (const float*)d_in[8];
    float* out = (float*)d_out;

    int N = in_sizes[0] / 128;
    int E = in_sizes[1] / 2;

    k_prep<<<1, 64>>>(W_edge, att_edge);
    k_gemm<<<(N + 31) / 32, 256>>>(x, W, N);
    k_att_nodes<<<(N * 4 + 255) / 256, 256>>>(att_src, att_dst, N);
    k_init<<<(N * 4 + 255) / 256, 256>>>(N);
    k_edge_alpha<<<(E + 255) / 256, 256>>>(ei, (const float4*)ea, E);
    k_edge_exp<<<(E + 255) / 256, 256>>>(ei, E);
    k_node_finalize<<<N, 64>>>(bias, out, N);
    k_scatter<<<(E + 7) / 8, 256>>>(ei, out, E);
}

// round 2
// speedup vs baseline: 1.9653x; 1.9653x over previous
#include <cuda_runtime.h>
#include <stdint.h>

#define NMAX 50000
#define EMAX 1600000

// ---------------- scratch (device globals; no allocation) ----------------
__device__ float4 g_h4[NMAX * 16];      // h [N,64]
__device__ float4 g_asrc4[NMAX];        // a_src [N,4]
__device__ float4 g_adst4[NMAX];        // a_dst [N,4]
__device__ float  g_v[64];              // v [16,4]  (d*4+h)
__device__ float  g_vsum[4];
__device__ float4 g_alpha4[EMAX];       // per-edge exp(logit) [E,4]
__device__ float4 g_denom4[NMAX];       // softmax denominators -> reciprocals [N,4]

__device__ __forceinline__ float lrelu(float a) { return a > 0.f ? a : 0.2f * a; }

__device__ __forceinline__ void red_add_v4(float* addr, float a, float b, float c, float d) {
    asm volatile("red.global.add.v4.f32 [%0], {%1,%2,%3,%4};"
                 :: "l"(addr), "f"(a), "f"(b), "f"(c), "f"(d) : "memory");
}

// ---------------- K1: v[d,h] = sum_c W_edge[d,h*16+c]*att_edge[h,c] ------
__global__ void k_prep(const float* __restrict__ We, const float* __restrict__ ae) {
    int t = threadIdx.x;   // 64 threads
    int d = t >> 2, h = t & 3;
    float s = 0.f;
#pragma unroll
    for (int c = 0; c < 16; c++) s += We[d * 64 + h * 16 + c] * ae[h * 16 + c];
    g_v[t] = s;
    __syncthreads();
    if (t < 4) {
        float ss = 0.f;
#pragma unroll
        for (int dd = 0; dd < 16; dd++) ss += g_v[dd * 4 + t];
        g_vsum[t] = ss;
    }
}

// ---------------- K2: h = x @ W  (x:[N,128], W:[128,64]) -----------------
// block 256: tile 64 nodes x 64 channels, per-thread 4x4 register tile.
// dynamic smem: sW[128*64] + sx[64*132]
__global__ void k_gemm(const float* __restrict__ x, const float* __restrict__ W, int N) {
    extern __shared__ float smem[];
    float* sW = smem;             // 8192 floats
    float* sx = smem + 8192;      // 64*132 floats (pad 132 for bank-free column reads)
    int t = threadIdx.x;
    int n0 = blockIdx.x * 64;

    // load W (coalesced float4)
    for (int i = t; i < 2048; i += 256)
        reinterpret_cast<float4*>(sW)[i] = reinterpret_cast<const float4*>(W)[i];

    // load x tile (64 rows x 128), coalesced float4, guarded tail
    for (int i = t; i < 2048; i += 256) {
        int row = i >> 5;          // 32 float4 per row
        int col4 = i & 31;
        float4 v = make_float4(0.f, 0.f, 0.f, 0.f);
        if (n0 + row < N)
            v = reinterpret_cast<const float4*>(x)[(size_t)(n0 + row) * 32 + col4];
        float* dp = sx + row * 132 + col4 * 4;
        dp[0] = v.x; dp[1] = v.y; dp[2] = v.z; dp[3] = v.w;
    }
    __syncthreads();

    int tc = t & 15;          // channel group (4 channels)
    int tn = t >> 4;          // node group (4 nodes)
    const float* xr = sx + (tn * 4) * 132;
    float acc[4][4];
#pragma unroll
    for (int i = 0; i < 4; i++)
#pragma unroll
        for (int j = 0; j < 4; j++) acc[i][j] = 0.f;

#pragma unroll 4
    for (int k = 0; k < 128; k++) {
        float4 wv = *reinterpret_cast<const float4*>(sW + k * 64 + tc * 4);
        float x0 = xr[k], x1 = xr[132 + k], x2 = xr[264 + k], x3 = xr[396 + k];
        acc[0][0] += x0 * wv.x; acc[0][1] += x0 * wv.y; acc[0][2] += x0 * wv.z; acc[0][3] += x0 * wv.w;
        acc[1][0] += x1 * wv.x; acc[1][1] += x1 * wv.y; acc[1][2] += x1 * wv.z; acc[1][3] += x1 * wv.w;
        acc[2][0] += x2 * wv.x; acc[2][1] += x2 * wv.y; acc[2][2] += x2 * wv.z; acc[2][3] += x2 * wv.w;
        acc[3][0] += x3 * wv.x; acc[3][1] += x3 * wv.y; acc[3][2] += x3 * wv.z; acc[3][3] += x3 * wv.w;
    }

#pragma unroll
    for (int i = 0; i < 4; i++) {
        int n = n0 + tn * 4 + i;
        if (n < N)
            reinterpret_cast<float4*>((float*)g_h4 + n * 64)[tc] =
                make_float4(acc[i][0], acc[i][1], acc[i][2], acc[i][3]);
    }
}

// ---------------- K3: a_src/a_dst per (n,h); zero denom -------------------
__global__ void k_att_nodes(const float* __restrict__ att_src,
                            const float* __restrict__ att_dst, int N) {
    __shared__ float ssrc[64], sdst[64];
    if (threadIdx.x < 64) { ssrc[threadIdx.x] = att_src[threadIdx.x]; sdst[threadIdx.x] = att_dst[threadIdx.x]; }
    __syncthreads();
    int t = blockIdx.x * blockDim.x + threadIdx.x;
    if (t >= N * 4) return;
    int n = t >> 2, h = t & 3;
    const float* hv = (const float*)g_h4 + n * 64 + h * 16;
    float s1 = 0.f, s2 = 0.f;
#pragma unroll
    for (int c = 0; c < 16; c++) {
        float v = hv[c];
        s1 += v * ssrc[h * 16 + c];
        s2 += v * sdst[h * 16 + c];
    }
    ((float*)g_asrc4)[t] = s1;
    ((float*)g_adst4)[t] = s2;
    ((float*)g_denom4)[t] = 0.f;
}

// ---------------- K4: per-edge exp(lrelu(logit)) + denom accumulate -------
__global__ void k_edge(const int* __restrict__ ei, const float4* __restrict__ ea4, int E) {
    __shared__ float sv[64];
    if (threadIdx.x < 64) sv[threadIdx.x] = g_v[threadIdx.x];
    __syncthreads();
    int e = blockIdx.x * blockDim.x + threadIdx.x;
    if (e >= E) return;
    int src = ei[e], dst = ei[E + e];
    float a0 = 0.f, a1 = 0.f, a2 = 0.f, a3 = 0.f;
#pragma unroll
    for (int k = 0; k < 4; k++) {
        float4 q = ea4[e * 4 + k];
        const float* vp = sv + k * 16;
        a0 += q.x * vp[0] + q.y * vp[4] + q.z * vp[8]  + q.w * vp[12];
        a1 += q.x * vp[1] + q.y * vp[5] + q.z * vp[9]  + q.w * vp[13];
        a2 += q.x * vp[2] + q.y * vp[6] + q.z * vp[10] + q.w * vp[14];
        a3 += q.x * vp[3] + q.y * vp[7] + q.z * vp[11] + q.w * vp[15];
    }
    float4 as = g_asrc4[src];
    float4 ad = g_adst4[dst];
    float4 ex;
    ex.x = __expf(lrelu(as.x + ad.x + a0));
    ex.y = __expf(lrelu(as.y + ad.y + a1));
    ex.z = __expf(lrelu(as.z + ad.z + a2));
    ex.w = __expf(lrelu(as.w + ad.w + a3));
    g_alpha4[e] = ex;
    red_add_v4((float*)(g_denom4 + dst), ex.x, ex.y, ex.z, ex.w);
}

// ---------------- K5: self-loop into denom, store reciprocal, seed out ----
__global__ void k_node_finalize(const float* __restrict__ bias, float* __restrict__ out, int N) {
    int n = blockIdx.x;
    int t = threadIdx.x;   // 64
    __shared__ float satt[4];
    if (t < 4) {
        float a = ((const float*)g_asrc4)[n * 4 + t] + ((const float*)g_adst4)[n * 4 + t] + g_vsum[t];
        float ex = __expf(lrelu(a));
        float dn = ((const float*)g_denom4)[n * 4 + t] + ex;
        float r = 1.f / dn;
        ((float*)g_denom4)[n * 4 + t] = r;   // store reciprocal for scatter
        satt[t] = ex * r;
    }
    __syncthreads();
    out[n * 64 + t] = satt[t >> 4] * ((const float*)g_h4)[n * 64 + t] + __ldg(bias + t);
}

// ---------------- K6: weighted scatter-add, 4 threads/edge, red.v4 --------
__global__ void k_scatter(const int* __restrict__ ei, float* __restrict__ out, int E) {
    int idx = blockIdx.x * blockDim.x + threadIdx.x;
    int e = idx >> 2;
    if (e >= E) return;
    int h = idx & 3;
    int src = __ldg(ei + e), dst = __ldg(ei + E + e);
    float w = ((const float*)g_alpha4)[e * 4 + h] * ((const float*)g_denom4)[dst * 4 + h];
    const float4* hp = (const float4*)((const float*)g_h4 + src * 64 + h * 16);
    float* o = out + dst * 64 + h * 16;
#pragma unroll
    for (int j = 0; j < 4; j++) {
        float4 v = hp[j];
        red_add_v4(o + j * 4, w * v.x, w * v.y, w * v.z, w * v.w);
    }
}

// ---------------- launch ---------------------------------------------------
extern "C" void kernel_launch(void* const* d_in, const int* in_sizes, int n_in,
                              void* d_out, int out_size) {
    const float* x        = (const float*)d_in[0];
    const int*   ei       = (const int*)d_in[1];
    const float* ea       = (const float*)d_in[2];
    const float* W        = (const float*)d_in[3];
    const float* att_src  = (const float*)d_in[4];
    const float* att_dst  = (const float*)d_in[5];
    const float* W_edge   = (const float*)d_in[6];
    const float* att_edge = (const float*)d_in[7];
    const float* bias     = (const float*)d_in[8];
    float* out = (float*)d_out;

    int N = in_sizes[0] / 128;
    int E = in_sizes[1] / 2;

    const int gemm_smem = (8192 + 64 * 132) * 4;   // 66560 bytes
    cudaFuncSetAttribute(k_gemm, cudaFuncAttributeMaxDynamicSharedMemorySize, gemm_smem);

    k_prep<<<1, 64>>>(W_edge, att_edge);
    k_gemm<<<(N + 63) / 64, 256, gemm_smem>>>(x, W, N);
    k_att_nodes<<<(N * 4 + 255) / 256, 256>>>(att_src, att_dst, N);
    k_edge<<<(E + 255) / 256, 256>>>(ei, (const float4*)ea, E);
    k_node_finalize<<<N, 64>>>(bias, out, N);
    k_scatter<<<(E * 4 + 255) / 256, 256>>>(ei, out, E);
}

// round 3
// speedup vs baseline: 3.0058x; 1.5294x over previous
#include <cuda_runtime.h>
#include <stdint.h>

#define NMAX 50000
#define EMAX 1600000
#define SCAN_CHUNK 512

// ---------------- scratch (device globals; no allocation) ----------------
__device__ float4 g_h4[NMAX * 16];      // h [N,64]
__device__ float4 g_asrc4[NMAX];        // a_src [N,4]
__device__ float4 g_adst4[NMAX];        // a_dst [N,4]
__device__ float  g_v[64];              // v [16,4]  (d*4+h)
__device__ float  g_vsum[4];
__device__ int    g_cnt[NMAX];          // in-degree
__device__ int    g_off[NMAX];          // CSR offsets
__device__ int    g_cur[NMAX];          // write cursors
__device__ int    g_bsum[256];          // scan block sums
__device__ int    g_src_s[EMAX];        // dst-sorted src ids
__device__ float4 g_ex_s[EMAX];         // dst-sorted exp(logit) [E,4]

__device__ __forceinline__ float lrelu(float a) { return a > 0.f ? a : 0.2f * a; }

// ---------------- K1: v[d,h] = sum_c W_edge[d,h*16+c]*att_edge[h,c] ------
__global__ void k_prep(const float* __restrict__ We, const float* __restrict__ ae) {
    int t = threadIdx.x;   // 64 threads
    int d = t >> 2, h = t & 3;
    float s = 0.f;
#pragma unroll
    for (int c = 0; c < 16; c++) s += We[d * 64 + h * 16 + c] * ae[h * 16 + c];
    g_v[t] = s;
    __syncthreads();
    if (t < 4) {
        float ss = 0.f;
#pragma unroll
        for (int dd = 0; dd < 16; dd++) ss += g_v[dd * 4 + t];
        g_vsum[t] = ss;
    }
}

// ---------------- K2: h = x @ W  (x:[N,128], W:[128,64]) -----------------
__global__ void k_gemm(const float* __restrict__ x, const float* __restrict__ W, int N) {
    extern __shared__ float smem[];
    float* sW = smem;             // 8192 floats
    float* sx = smem + 8192;      // 64*132 floats
    int t = threadIdx.x;
    int n0 = blockIdx.x * 64;

    for (int i = t; i < 2048; i += 256)
        reinterpret_cast<float4*>(sW)[i] = reinterpret_cast<const float4*>(W)[i];

    for (int i = t; i < 2048; i += 256) {
        int row = i >> 5;
        int col4 = i & 31;
        float4 v = make_float4(0.f, 0.f, 0.f, 0.f);
        if (n0 + row < N)
            v = reinterpret_cast<const float4*>(x)[(size_t)(n0 + row) * 32 + col4];
        float* dp = sx + row * 132 + col4 * 4;
        dp[0] = v.x; dp[1] = v.y; dp[2] = v.z; dp[3] = v.w;
    }
    __syncthreads();

    int tc = t & 15;
    int tn = t >> 4;
    const float* xr = sx + (tn * 4) * 132;
    float acc[4][4];
#pragma unroll
    for (int i = 0; i < 4; i++)
#pragma unroll
        for (int j = 0; j < 4; j++) acc[i][j] = 0.f;

#pragma unroll 4
    for (int k = 0; k < 128; k++) {
        float4 wv = *reinterpret_cast<const float4*>(sW + k * 64 + tc * 4);
        float x0 = xr[k], x1 = xr[132 + k], x2 = xr[264 + k], x3 = xr[396 + k];
        acc[0][0] += x0 * wv.x; acc[0][1] += x0 * wv.y; acc[0][2] += x0 * wv.z; acc[0][3] += x0 * wv.w;
        acc[1][0] += x1 * wv.x; acc[1][1] += x1 * wv.y; acc[1][2] += x1 * wv.z; acc[1][3] += x1 * wv.w;
        acc[2][0] += x2 * wv.x; acc[2][1] += x2 * wv.y; acc[2][2] += x2 * wv.z; acc[2][3] += x2 * wv.w;
        acc[3][0] += x3 * wv.x; acc[3][1] += x3 * wv.y; acc[3][2] += x3 * wv.z; acc[3][3] += x3 * wv.w;
    }

#pragma unroll
    for (int i = 0; i < 4; i++) {
        int n = n0 + tn * 4 + i;
        if (n < N)
            reinterpret_cast<float4*>((float*)g_h4 + n * 64)[tc] =
                make_float4(acc[i][0], acc[i][1], acc[i][2], acc[i][3]);
    }
}

// ---------------- K3: a_src/a_dst per (n,h); zero counts ------------------
__global__ void k_att_nodes(const float* __restrict__ att_src,
                            const float* __restrict__ att_dst, int N) {
    __shared__ float ssrc[64], sdst[64];
    if (threadIdx.x < 64) { ssrc[threadIdx.x] = att_src[threadIdx.x]; sdst[threadIdx.x] = att_dst[threadIdx.x]; }
    __syncthreads();
    int t = blockIdx.x * blockDim.x + threadIdx.x;
    if (t < N) g_cnt[t] = 0;
    if (t >= N * 4) return;
    int n = t >> 2, h = t & 3;
    const float* hv = (const float*)g_h4 + n * 64 + h * 16;
    float s1 = 0.f, s2 = 0.f;
#pragma unroll
    for (int c = 0; c < 16; c++) {
        float v = hv[c];
        s1 += v * ssrc[h * 16 + c];
        s2 += v * sdst[h * 16 + c];
    }
    ((float*)g_asrc4)[t] = s1;
    ((float*)g_adst4)[t] = s2;
}

// ---------------- K4: in-degree histogram ---------------------------------
__global__ void k_hist(const int* __restrict__ ei, int E) {
    int e = blockIdx.x * blockDim.x + threadIdx.x;
    if (e >= E) return;
    atomicAdd(&g_cnt[ei[E + e]], 1);
}

// ---------------- K5-7: exclusive scan over g_cnt -> g_off / g_cur --------
__global__ void k_scan1(int N) {
    __shared__ int s[SCAN_CHUNK];
    int g = blockIdx.x * SCAN_CHUNK + threadIdx.x;
    int v = (g < N) ? g_cnt[g] : 0;
    s[threadIdx.x] = v;
    __syncthreads();
    for (int d = 1; d < SCAN_CHUNK; d <<= 1) {
        int tv = (threadIdx.x >= d) ? s[threadIdx.x - d] : 0;
        __syncthreads();
        s[threadIdx.x] += tv;
        __syncthreads();
    }
    if (g < N) g_off[g] = s[threadIdx.x] - v;      // exclusive
    if (threadIdx.x == SCAN_CHUNK - 1) g_bsum[blockIdx.x] = s[SCAN_CHUNK - 1];
}

__global__ void k_scan2(int nb) {
    __shared__ int s[256];
    int v = (threadIdx.x < nb) ? g_bsum[threadIdx.x] : 0;
    s[threadIdx.x] = v;
    __syncthreads();
    for (int d = 1; d < 256; d <<= 1) {
        int tv = (threadIdx.x >= d) ? s[threadIdx.x - d] : 0;
        __syncthreads();
        s[threadIdx.x] += tv;
        __syncthreads();
    }
    if (threadIdx.x < nb) g_bsum[threadIdx.x] = s[threadIdx.x] - v;   // exclusive
}

__global__ void k_scan3(int N) {
    int g = blockIdx.x * SCAN_CHUNK + threadIdx.x;
    if (g < N) {
        int o = g_off[g] + g_bsum[blockIdx.x];
        g_off[g] = o;
        g_cur[g] = o;
    }
}

// ---------------- K8: per-edge exp(lrelu(logit)) + CSR permute ------------
__global__ void k_edge(const int* __restrict__ ei, const float4* __restrict__ ea4, int E) {
    __shared__ float sv[64];
    if (threadIdx.x < 64) sv[threadIdx.x] = g_v[threadIdx.x];
    __syncthreads();
    int e = blockIdx.x * blockDim.x + threadIdx.x;
    if (e >= E) return;
    int src = ei[e], dst = ei[E + e];
    float a0 = 0.f, a1 = 0.f, a2 = 0.f, a3 = 0.f;
#pragma unroll
    for (int k = 0; k < 4; k++) {
        float4 q = __ldcs(ea4 + e * 4 + k);   // stream, evict-first
        const float* vp = sv + k * 16;
        a0 += q.x * vp[0] + q.y * vp[4] + q.z * vp[8]  + q.w * vp[12];
        a1 += q.x * vp[1] + q.y * vp[5] + q.z * vp[9]  + q.w * vp[13];
        a2 += q.x * vp[2] + q.y * vp[6] + q.z * vp[10] + q.w * vp[14];
        a3 += q.x * vp[3] + q.y * vp[7] + q.z * vp[11] + q.w * vp[15];
    }
    float4 as = g_asrc4[src];
    float4 ad = g_adst4[dst];
    float4 ex;
    ex.x = __expf(lrelu(as.x + ad.x + a0));
    ex.y = __expf(lrelu(as.y + ad.y + a1));
    ex.z = __expf(lrelu(as.z + ad.z + a2));
    ex.w = __expf(lrelu(as.w + ad.w + a3));
    int pos = atomicAdd(&g_cur[dst], 1);
    g_src_s[pos] = src;
    g_ex_s[pos] = ex;
}

// ---------------- K9: per-node register aggregation (no atomics) ----------
__global__ void k_agg(const float* __restrict__ bias, float* __restrict__ out, int N) {
    int n = (blockIdx.x * blockDim.x + threadIdx.x) >> 5;
    int lane = threadIdx.x & 31;
    if (n >= N) return;
    int off = g_off[n], deg = g_cnt[n];
    int h0 = lane >> 4;        // head of channel `lane`      (0..1)
    int h1 = 2 + h0;           // head of channel `lane+32`   (2..3)

    float acc0 = 0.f, acc1 = 0.f, dn0 = 0.f, dn1 = 0.f;
    const float* exs = (const float*)g_ex_s;

    int i = 0;
    for (; i + 2 <= deg; i += 2) {
        int sA = __ldg(g_src_s + off + i);
        int sB = __ldg(g_src_s + off + i + 1);
        float wA0 = __ldg(exs + (off + i) * 4 + h0);
        float wA1 = __ldg(exs + (off + i) * 4 + h1);
        float wB0 = __ldg(exs + (off + i + 1) * 4 + h0);
        float wB1 = __ldg(exs + (off + i + 1) * 4 + h1);
        const float* hA = (const float*)g_h4 + sA * 64;
        const float* hB = (const float*)g_h4 + sB * 64;
        float hA0 = __ldg(hA + lane), hA1 = __ldg(hA + 32 + lane);
        float hB0 = __ldg(hB + lane), hB1 = __ldg(hB + 32 + lane);
        acc0 += wA0 * hA0 + wB0 * hB0;
        acc1 += wA1 * hA1 + wB1 * hB1;
        dn0 += wA0 + wB0;
        dn1 += wA1 + wB1;
    }
    if (i < deg) {
        int sA = __ldg(g_src_s + off + i);
        float wA0 = __ldg(exs + (off + i) * 4 + h0);
        float wA1 = __ldg(exs + (off + i) * 4 + h1);
        const float* hA = (const float*)g_h4 + sA * 64;
        acc0 += wA0 * __ldg(hA + lane);
        acc1 += wA1 * __ldg(hA + 32 + lane);
        dn0 += wA0;
        dn1 += wA1;
    }

    // self loop
    float sl0 = ((const float*)g_asrc4)[n * 4 + h0] + ((const float*)g_adst4)[n * 4 + h0] + g_vsum[h0];
    float sl1 = ((const float*)g_asrc4)[n * 4 + h1] + ((const float*)g_adst4)[n * 4 + h1] + g_vsum[h1];
    float es0 = __expf(lrelu(sl0));
    float es1 = __expf(lrelu(sl1));
    const float* hn = (const float*)g_h4 + n * 64;
    float o0 = (acc0 + es0 * hn[lane])      / (dn0 + es0) + __ldg(bias + lane);
    float o1 = (acc1 + es1 * hn[32 + lane]) / (dn1 + es1) + __ldg(bias + 32 + lane);
    out[n * 64 + lane]      = o0;
    out[n * 64 + 32 + lane] = o1;
}

// ---------------- launch ---------------------------------------------------
extern "C" void kernel_launch(void* const* d_in, const int* in_sizes, int n_in,
                              void* d_out, int out_size) {
    const float* x        = (const float*)d_in[0];
    const int*   ei       = (const int*)d_in[1];
    const float* ea       = (const float*)d_in[2];
    const float* W        = (const float*)d_in[3];
    const float* att_src  = (const float*)d_in[4];
    const float* att_dst  = (const float*)d_in[5];
    const float* W_edge   = (const float*)d_in[6];
    const float* att_edge = (const float*)d_in[7];
    const float* bias     = (const float*)d_in[8];
    float* out = (float*)d_out;

    int N = in_sizes[0] / 128;
    int E = in_sizes[1] / 2;
    int nscan = (N + SCAN_CHUNK - 1) / SCAN_CHUNK;

    const int gemm_smem = (8192 + 64 * 132) * 4;
    cudaFuncSetAttribute(k_gemm, cudaFuncAttributeMaxDynamicSharedMemorySize, gemm_smem);

    k_prep<<<1, 64>>>(W_edge, att_edge);
    k_gemm<<<(N + 63) / 64, 256, gemm_smem>>>(x, W, N);
    k_att_nodes<<<(N * 4 + 255) / 256, 256>>>(att_src, att_dst, N);
    k_hist<<<(E + 255) / 256, 256>>>(ei, E);
    k_scan1<<<nscan, SCAN_CHUNK>>>(N);
    k_scan2<<<1, 256>>>(nscan);
    k_scan3<<<nscan, SCAN_CHUNK>>>(N);
    k_edge<<<(E + 255) / 256, 256>>>(ei, (const float4*)ea, E);
    k_agg<<<(N * 32 + 255) / 256, 256>>>(bias, out, N);
}

// round 4
// speedup vs baseline: 3.0651x; 1.0197x over previous
#include <cuda_runtime.h>
#include <stdint.h>

#define NMAX 50000
#define EMAX 1600000
#define SCAN_CHUNK 512

// ---------------- scratch (device globals; no allocation) ----------------
__device__ float4 g_h4[NMAX * 16];      // h [N,64]
__device__ float4 g_asrc4[NMAX];        // a_src [N,4]
__device__ float4 g_adst4[NMAX];        // a_dst [N,4]
__device__ float  g_v[64];              // v [16,4]  (d*4+h)
__device__ float  g_vsum[4];
__device__ int    g_cnt[NMAX];          // in-degree
__device__ int    g_off[NMAX];          // CSR offsets
__device__ int    g_cur[NMAX];          // write cursors
__device__ int    g_bsum[256];          // scan block sums
__device__ int    g_src_s[EMAX];        // dst-sorted src ids
__device__ float4 g_ex_s[EMAX];         // dst-sorted exp(logit) [E,4]

__device__ __forceinline__ float lrelu(float a) { return a > 0.f ? a : 0.2f * a; }

// ---------------- K1 (stream B): zero g_cnt; block 0 computes v/vsum -----
__global__ void k_prep(const float* __restrict__ We, const float* __restrict__ ae, int N) {
    __shared__ float sv[64];
    int g = blockIdx.x * blockDim.x + threadIdx.x;
    if (g < N) g_cnt[g] = 0;
    if (blockIdx.x == 0) {
        int t = threadIdx.x;
        if (t < 64) {
            int d = t >> 2, h = t & 3;
            float s = 0.f;
#pragma unroll
            for (int c = 0; c < 16; c++) s += We[d * 64 + h * 16 + c] * ae[h * 16 + c];
            sv[t] = s;
            g_v[t] = s;
        }
        __syncthreads();
        if (t < 4) {
            float ss = 0.f;
#pragma unroll
            for (int dd = 0; dd < 16; dd++) ss += sv[dd * 4 + t];
            g_vsum[t] = ss;
        }
    }
}

// ---------------- K2 (stream B): in-degree histogram, 8 edges/thread ------
__global__ void k_hist(const int* __restrict__ ei, int E) {
    int base = (blockIdx.x * blockDim.x + threadIdx.x) * 8;
    if (base >= E) return;
    const int* d = ei + E;
    if (base + 8 <= E && ((E & 3) == 0)) {
        int4 a = *reinterpret_cast<const int4*>(d + base);
        int4 b = *reinterpret_cast<const int4*>(d + base + 4);
        atomicAdd(&g_cnt[a.x], 1); atomicAdd(&g_cnt[a.y], 1);
        atomicAdd(&g_cnt[a.z], 1); atomicAdd(&g_cnt[a.w], 1);
        atomicAdd(&g_cnt[b.x], 1); atomicAdd(&g_cnt[b.y], 1);
        atomicAdd(&g_cnt[b.z], 1); atomicAdd(&g_cnt[b.w], 1);
    } else {
        for (int i = base; i < E && i < base + 8; i++) atomicAdd(&g_cnt[d[i]], 1);
    }
}

// ---------------- K3-5 (stream B): exclusive scan -> g_off / g_cur --------
__global__ void k_scan1(int N) {
    __shared__ int s[SCAN_CHUNK];
    int g = blockIdx.x * SCAN_CHUNK + threadIdx.x;
    int v = (g < N) ? g_cnt[g] : 0;
    s[threadIdx.x] = v;
    __syncthreads();
    for (int d = 1; d < SCAN_CHUNK; d <<= 1) {
        int tv = (threadIdx.x >= d) ? s[threadIdx.x - d] : 0;
        __syncthreads();
        s[threadIdx.x] += tv;
        __syncthreads();
    }
    if (g < N) g_off[g] = s[threadIdx.x] - v;      // exclusive
    if (threadIdx.x == SCAN_CHUNK - 1) g_bsum[blockIdx.x] = s[SCAN_CHUNK - 1];
}

__global__ void k_scan2(int nb) {
    __shared__ int s[256];
    int v = (threadIdx.x < nb) ? g_bsum[threadIdx.x] : 0;
    s[threadIdx.x] = v;
    __syncthreads();
    for (int d = 1; d < 256; d <<= 1) {
        int tv = (threadIdx.x >= d) ? s[threadIdx.x - d] : 0;
        __syncthreads();
        s[threadIdx.x] += tv;
        __syncthreads();
    }
    if (threadIdx.x < nb) g_bsum[threadIdx.x] = s[threadIdx.x] - v;   // exclusive
}

__global__ void k_scan3(int N) {
    int g = blockIdx.x * SCAN_CHUNK + threadIdx.x;
    if (g < N) {
        int o = g_off[g] + g_bsum[blockIdx.x];
        g_off[g] = o;
        g_cur[g] = o;
    }
}

// ---------------- K6 (stream A): h = x @ W --------------------------------
__global__ void k_gemm(const float* __restrict__ x, const float* __restrict__ W, int N) {
    extern __shared__ float smem[];
    float* sW = smem;             // 8192 floats
    float* sx = smem + 8192;      // 64*132 floats
    int t = threadIdx.x;
    int n0 = blockIdx.x * 64;

    for (int i = t; i < 2048; i += 256)
        reinterpret_cast<float4*>(sW)[i] = reinterpret_cast<const float4*>(W)[i];

    for (int i = t; i < 2048; i += 256) {
        int row = i >> 5;
        int col4 = i & 31;
        float4 v = make_float4(0.f, 0.f, 0.f, 0.f);
        if (n0 + row < N)
            v = reinterpret_cast<const float4*>(x)[(size_t)(n0 + row) * 32 + col4];
        float* dp = sx + row * 132 + col4 * 4;
        dp[0] = v.x; dp[1] = v.y; dp[2] = v.z; dp[3] = v.w;
    }
    __syncthreads();

    int tc = t & 15;
    int tn = t >> 4;
    const float* xr = sx + (tn * 4) * 132;
    float acc[4][4];
#pragma unroll
    for (int i = 0; i < 4; i++)
#pragma unroll
        for (int j = 0; j < 4; j++) acc[i][j] = 0.f;

#pragma unroll 4
    for (int k = 0; k < 128; k++) {
        float4 wv = *reinterpret_cast<const float4*>(sW + k * 64 + tc * 4);
        float x0 = xr[k], x1 = xr[132 + k], x2 = xr[264 + k], x3 = xr[396 + k];
        acc[0][0] += x0 * wv.x; acc[0][1] += x0 * wv.y; acc[0][2] += x0 * wv.z; acc[0][3] += x0 * wv.w;
        acc[1][0] += x1 * wv.x; acc[1][1] += x1 * wv.y; acc[1][2] += x1 * wv.z; acc[1][3] += x1 * wv.w;
        acc[2][0] += x2 * wv.x; acc[2][1] += x2 * wv.y; acc[2][2] += x2 * wv.z; acc[2][3] += x2 * wv.w;
        acc[3][0] += x3 * wv.x; acc[3][1] += x3 * wv.y; acc[3][2] += x3 * wv.z; acc[3][3] += x3 * wv.w;
    }

#pragma unroll
    for (int i = 0; i < 4; i++) {
        int n = n0 + tn * 4 + i;
        if (n < N)
            reinterpret_cast<float4*>((float*)g_h4 + n * 64)[tc] =
                make_float4(acc[i][0], acc[i][1], acc[i][2], acc[i][3]);
    }
}

// ---------------- K7 (stream A): a_src/a_dst per (n,h) --------------------
__global__ void k_att_nodes(const float* __restrict__ att_src,
                            const float* __restrict__ att_dst, int N) {
    __shared__ float ssrc[64], sdst[64];
    if (threadIdx.x < 64) { ssrc[threadIdx.x] = att_src[threadIdx.x]; sdst[threadIdx.x] = att_dst[threadIdx.x]; }
    __syncthreads();
    int t = blockIdx.x * blockDim.x + threadIdx.x;
    if (t >= N * 4) return;
    int n = t >> 2, h = t & 3;
    const float* hv = (const float*)g_h4 + n * 64 + h * 16;
    float s1 = 0.f, s2 = 0.f;
#pragma unroll
    for (int c = 0; c < 16; c++) {
        float v = hv[c];
        s1 += v * ssrc[h * 16 + c];
        s2 += v * sdst[h * 16 + c];
    }
    ((float*)g_asrc4)[t] = s1;
    ((float*)g_adst4)[t] = s2;
}

// ---------------- K8 (joined): per-edge exp(lrelu(logit)) + CSR permute ---
__global__ void k_edge(const int* __restrict__ ei, const float4* __restrict__ ea4, int E) {
    __shared__ float sv[64];
    if (threadIdx.x < 64) sv[threadIdx.x] = g_v[threadIdx.x];
    __syncthreads();
    int e = blockIdx.x * blockDim.x + threadIdx.x;
    if (e >= E) return;
    int src = ei[e], dst = ei[E + e];
    float a0 = 0.f, a1 = 0.f, a2 = 0.f, a3 = 0.f;
#pragma unroll
    for (int k = 0; k < 4; k++) {
        float4 q = __ldcs(ea4 + e * 4 + k);   // stream, evict-first
        const float* vp = sv + k * 16;
        a0 += q.x * vp[0] + q.y * vp[4] + q.z * vp[8]  + q.w * vp[12];
        a1 += q.x * vp[1] + q.y * vp[5] + q.z * vp[9]  + q.w * vp[13];
        a2 += q.x * vp[2] + q.y * vp[6] + q.z * vp[10] + q.w * vp[14];
        a3 += q.x * vp[3] + q.y * vp[7] + q.z * vp[11] + q.w * vp[15];
    }
    float4 as = g_asrc4[src];
    float4 ad = g_adst4[dst];
    float4 ex;
    ex.x = __expf(lrelu(as.x + ad.x + a0));
    ex.y = __expf(lrelu(as.y + ad.y + a1));
    ex.z = __expf(lrelu(as.z + ad.z + a2));
    ex.w = __expf(lrelu(as.w + ad.w + a3));
    int pos = atomicAdd(&g_cur[dst], 1);
    g_src_s[pos] = src;
    g_ex_s[pos] = ex;
}

// ---------------- K9: per-node register aggregation (no atomics) ----------
__global__ void k_agg(const float* __restrict__ bias, float* __restrict__ out, int N) {
    int n = (blockIdx.x * blockDim.x + threadIdx.x) >> 5;
    int lane = threadIdx.x & 31;
    if (n >= N) return;
    int off = g_off[n], deg = g_cnt[n];
    int h0 = lane >> 4;        // head of channel `lane`      (0..1)
    int h1 = 2 + h0;           // head of channel `lane+32`   (2..3)

    float acc0 = 0.f, acc1 = 0.f, dn0 = 0.f, dn1 = 0.f;
    const float* exs = (const float*)g_ex_s;

    int i = 0;
    for (; i + 4 <= deg; i += 4) {
        int s0 = __ldg(g_src_s + off + i);
        int s1 = __ldg(g_src_s + off + i + 1);
        int s2 = __ldg(g_src_s + off + i + 2);
        int s3 = __ldg(g_src_s + off + i + 3);
        float w00 = __ldg(exs + (off + i) * 4 + h0),     w01 = __ldg(exs + (off + i) * 4 + h1);
        float w10 = __ldg(exs + (off + i + 1) * 4 + h0), w11 = __ldg(exs + (off + i + 1) * 4 + h1);
        float w20 = __ldg(exs + (off + i + 2) * 4 + h0), w21 = __ldg(exs + (off + i + 2) * 4 + h1);
        float w30 = __ldg(exs + (off + i + 3) * 4 + h0), w31 = __ldg(exs + (off + i + 3) * 4 + h1);
        const float* p0 = (const float*)g_h4 + s0 * 64;
        const float* p1 = (const float*)g_h4 + s1 * 64;
        const float* p2 = (const float*)g_h4 + s2 * 64;
        const float* p3 = (const float*)g_h4 + s3 * 64;
        float a0 = __ldg(p0 + lane), b0 = __ldg(p0 + 32 + lane);
        float a1 = __ldg(p1 + lane), b1 = __ldg(p1 + 32 + lane);
        float a2 = __ldg(p2 + lane), b2 = __ldg(p2 + 32 + lane);
        float a3 = __ldg(p3 + lane), b3 = __ldg(p3 + 32 + lane);
        acc0 += w00 * a0 + w10 * a1 + w20 * a2 + w30 * a3;
        acc1 += w01 * b0 + w11 * b1 + w21 * b2 + w31 * b3;
        dn0  += w00 + w10 + w20 + w30;
        dn1  += w01 + w11 + w21 + w31;
    }
    for (; i < deg; i++) {
        int sA = __ldg(g_src_s + off + i);
        float wA0 = __ldg(exs + (off + i) * 4 + h0);
        float wA1 = __ldg(exs + (off + i) * 4 + h1);
        const float* hA = (const float*)g_h4 + sA * 64;
        acc0 += wA0 * __ldg(hA + lane);
        acc1 += wA1 * __ldg(hA + 32 + lane);
        dn0 += wA0;
        dn1 += wA1;
    }

    // self loop
    float sl0 = ((const float*)g_asrc4)[n * 4 + h0] + ((const float*)g_adst4)[n * 4 + h0] + g_vsum[h0];
    float sl1 = ((const float*)g_asrc4)[n * 4 + h1] + ((const float*)g_adst4)[n * 4 + h1] + g_vsum[h1];
    float es0 = __expf(lrelu(sl0));
    float es1 = __expf(lrelu(sl1));
    const float* hn = (const float*)g_h4 + n * 64;
    float o0 = (acc0 + es0 * hn[lane])      / (dn0 + es0) + __ldg(bias + lane);
    float o1 = (acc1 + es1 * hn[32 + lane]) / (dn1 + es1) + __ldg(bias + 32 + lane);
    out[n * 64 + lane]      = o0;
    out[n * 64 + 32 + lane] = o1;
}

// ---------------- launch ---------------------------------------------------
extern "C" void kernel_launch(void* const* d_in, const int* in_sizes, int n_in,
                              void* d_out, int out_size) {
    const float* x        = (const float*)d_in[0];
    const int*   ei       = (const int*)d_in[1];
    const float* ea       = (const float*)d_in[2];
    const float* W        = (const float*)d_in[3];
    const float* att_src  = (const float*)d_in[4];
    const float* att_dst  = (const float*)d_in[5];
    const float* W_edge   = (const float*)d_in[6];
    const float* att_edge = (const float*)d_in[7];
    const float* bias     = (const float*)d_in[8];
    float* out = (float*)d_out;

    int N = in_sizes[0] / 128;
    int E = in_sizes[1] / 2;
    int nscan = (N + SCAN_CHUNK - 1) / SCAN_CHUNK;

    const int gemm_smem = (8192 + 64 * 132) * 4;

    // one-time setup (runs on the un-captured correctness call first)
    static cudaStream_t sB = nullptr;
    static cudaEvent_t evF = nullptr, evJ = nullptr;
    if (!sB) {
        cudaFuncSetAttribute(k_gemm, cudaFuncAttributeMaxDynamicSharedMemorySize, gemm_smem);
        cudaStreamCreateWithFlags(&sB, cudaStreamNonBlocking);
        cudaEventCreateWithFlags(&evF, cudaEventDisableTiming);
        cudaEventCreateWithFlags(&evJ, cudaEventDisableTiming);
    }

    // fork: chain B (CSR build) runs concurrently with chain A (gemm/att)
    cudaEventRecord(evF, 0);
    cudaStreamWaitEvent(sB, evF, 0);

    // chain B
    k_prep<<<(N + 255) / 256, 256, 0, sB>>>(W_edge, att_edge, N);
    k_hist<<<(E + 2047) / 2048, 256, 0, sB>>>(ei, E);
    k_scan1<<<nscan, SCAN_CHUNK, 0, sB>>>(N);
    k_scan2<<<1, 256, 0, sB>>>(nscan);
    k_scan3<<<nscan, SCAN_CHUNK, 0, sB>>>(N);

    // chain A
    k_gemm<<<(N + 63) / 64, 256, gemm_smem>>>(x, W, N);
    k_att_nodes<<<(N * 4 + 255) / 256, 256>>>(att_src, att_dst, N);

    // join
    cudaEventRecord(evJ, sB);
    cudaStreamWaitEvent(0, evJ, 0);

    k_edge<<<(E + 255) / 256, 256>>>(ei, (const float4*)ea, E);
    k_agg<<<(N * 32 + 255) / 256, 256>>>(bias, out, N);
}

// round 5
// speedup vs baseline: 3.4335x; 1.1202x over previous
#include <cuda_runtime.h>
#include <cuda_fp16.h>
#include <stdint.h>

#define NMAX 50000
#define EMAX 1600000
#define SCAN_CHUNK 512

// ---------------- scratch (device globals; no allocation) ----------------
__device__ float4  g_h4[NMAX * 16];       // h [N,64] fp32 (self-loop term)
__device__ __half2 g_h2[NMAX * 32];       // h [N,64] fp16 (agg gather)
__device__ float4  g_asrc4[NMAX];         // a_src [N,4]
__device__ float4  g_adst4[NMAX];         // a_dst [N,4]
__device__ float   g_v[64];               // v [16,4]  (d*4+h)
__device__ float   g_vsum[4];
__device__ int     g_cnt[NMAX];           // in-degree
__device__ int     g_off[NMAX];           // CSR offsets
__device__ int     g_cur[NMAX];           // write cursors
__device__ int     g_bsum[256];           // scan block sums
__device__ int     g_src_s[EMAX];         // dst-sorted src ids
struct __align__(8) Ex4 { __half2 a, b; };
__device__ Ex4     g_exs[EMAX];           // dst-sorted exp(logit), 4 heads fp16

__device__ __forceinline__ float lrelu(float a) { return a > 0.f ? a : 0.2f * a; }

// ---------------- K1 (stream B): zero g_cnt; block 0 computes v/vsum -----
__global__ void k_prep(const float* __restrict__ We, const float* __restrict__ ae, int N) {
    __shared__ float sv[64];
    int g = blockIdx.x * blockDim.x + threadIdx.x;
    if (g < N) g_cnt[g] = 0;
    if (blockIdx.x == 0) {
        int t = threadIdx.x;
        if (t < 64) {
            int d = t >> 2, h = t & 3;
            float s = 0.f;
#pragma unroll
            for (int c = 0; c < 16; c++) s += We[d * 64 + h * 16 + c] * ae[h * 16 + c];
            sv[t] = s;
            g_v[t] = s;
        }
        __syncthreads();
        if (t < 4) {
            float ss = 0.f;
#pragma unroll
            for (int dd = 0; dd < 16; dd++) ss += sv[dd * 4 + t];
            g_vsum[t] = ss;
        }
    }
}

// ---------------- K2 (stream B): in-degree histogram, 8 edges/thread ------
__global__ void k_hist(const int* __restrict__ ei, int E) {
    int base = (blockIdx.x * blockDim.x + threadIdx.x) * 8;
    if (base >= E) return;
    const int* d = ei + E;
    if (base + 8 <= E && ((E & 3) == 0)) {
        int4 a = *reinterpret_cast<const int4*>(d + base);
        int4 b = *reinterpret_cast<const int4*>(d + base + 4);
        atomicAdd(&g_cnt[a.x], 1); atomicAdd(&g_cnt[a.y], 1);
        atomicAdd(&g_cnt[a.z], 1); atomicAdd(&g_cnt[a.w], 1);
        atomicAdd(&g_cnt[b.x], 1); atomicAdd(&g_cnt[b.y], 1);
        atomicAdd(&g_cnt[b.z], 1); atomicAdd(&g_cnt[b.w], 1);
    } else {
        for (int i = base; i < E && i < base + 8; i++) atomicAdd(&g_cnt[d[i]], 1);
    }
}

// ---------------- K3-5 (stream B): exclusive scan -> g_off / g_cur --------
__global__ void k_scan1(int N) {
    __shared__ int s[SCAN_CHUNK];
    int g = blockIdx.x * SCAN_CHUNK + threadIdx.x;
    int v = (g < N) ? g_cnt[g] : 0;
    s[threadIdx.x] = v;
    __syncthreads();
    for (int d = 1; d < SCAN_CHUNK; d <<= 1) {
        int tv = (threadIdx.x >= d) ? s[threadIdx.x - d] : 0;
        __syncthreads();
        s[threadIdx.x] += tv;
        __syncthreads();
    }
    if (g < N) g_off[g] = s[threadIdx.x] - v;
    if (threadIdx.x == SCAN_CHUNK - 1) g_bsum[blockIdx.x] = s[SCAN_CHUNK - 1];
}

__global__ void k_scan2(int nb) {
    __shared__ int s[256];
    int v = (threadIdx.x < nb) ? g_bsum[threadIdx.x] : 0;
    s[threadIdx.x] = v;
    __syncthreads();
    for (int d = 1; d < 256; d <<= 1) {
        int tv = (threadIdx.x >= d) ? s[threadIdx.x - d] : 0;
        __syncthreads();
        s[threadIdx.x] += tv;
        __syncthreads();
    }
    if (threadIdx.x < nb) g_bsum[threadIdx.x] = s[threadIdx.x] - v;
}

__global__ void k_scan3(int N) {
    int g = blockIdx.x * SCAN_CHUNK + threadIdx.x;
    if (g < N) {
        int o = g_off[g] + g_bsum[blockIdx.x];
        g_off[g] = o;
        g_cur[g] = o;
    }
}

// ---------------- K6 (stream A): h = x @ W, fused a_src/a_dst epilogue ----
__global__ void k_gemm(const float* __restrict__ x, const float* __restrict__ W,
                       const float* __restrict__ att_src, const float* __restrict__ att_dst,
                       int N) {
    extern __shared__ float smem[];
    float* sW = smem;             // 8192 floats
    float* sx = smem + 8192;      // 64*132 floats
    int t = threadIdx.x;
    int n0 = blockIdx.x * 64;

    for (int i = t; i < 2048; i += 256)
        reinterpret_cast<float4*>(sW)[i] = reinterpret_cast<const float4*>(W)[i];

    for (int i = t; i < 2048; i += 256) {
        int row = i >> 5;
        int col4 = i & 31;
        float4 v = make_float4(0.f, 0.f, 0.f, 0.f);
        if (n0 + row < N)
            v = reinterpret_cast<const float4*>(x)[(size_t)(n0 + row) * 32 + col4];
        float* dp = sx + row * 132 + col4 * 4;
        dp[0] = v.x; dp[1] = v.y; dp[2] = v.z; dp[3] = v.w;
    }
    __syncthreads();

    int tc = t & 15;          // channel group (4 channels: tc*4..tc*4+3)
    int tn = t >> 4;          // node group (4 nodes)
    const float* xr = sx + (tn * 4) * 132;
    float acc[4][4];
#pragma unroll
    for (int i = 0; i < 4; i++)
#pragma unroll
        for (int j = 0; j < 4; j++) acc[i][j] = 0.f;

#pragma unroll 4
    for (int k = 0; k < 128; k++) {
        float4 wv = *reinterpret_cast<const float4*>(sW + k * 64 + tc * 4);
        float x0 = xr[k], x1 = xr[132 + k], x2 = xr[264 + k], x3 = xr[396 + k];
        acc[0][0] += x0 * wv.x; acc[0][1] += x0 * wv.y; acc[0][2] += x0 * wv.z; acc[0][3] += x0 * wv.w;
        acc[1][0] += x1 * wv.x; acc[1][1] += x1 * wv.y; acc[1][2] += x1 * wv.z; acc[1][3] += x1 * wv.w;
        acc[2][0] += x2 * wv.x; acc[2][1] += x2 * wv.y; acc[2][2] += x2 * wv.z; acc[2][3] += x2 * wv.w;
        acc[3][0] += x3 * wv.x; acc[3][1] += x3 * wv.y; acc[3][2] += x3 * wv.z; acc[3][3] += x3 * wv.w;
    }

    // store h fp32 + fp16 copy
#pragma unroll
    for (int i = 0; i < 4; i++) {
        int n = n0 + tn * 4 + i;
        if (n < N) {
            reinterpret_cast<float4*>((float*)g_h4 + n * 64)[tc] =
                make_float4(acc[i][0], acc[i][1], acc[i][2], acc[i][3]);
            __half2 p0 = __floats2half2_rn(acc[i][0], acc[i][1]);
            __half2 p1 = __floats2half2_rn(acc[i][2], acc[i][3]);
            __half2* hp = g_h2 + n * 32 + tc * 2;
            hp[0] = p0; hp[1] = p1;
        }
    }

    // fused a_src/a_dst: dot over this thread's 4 channels, reduce across
    // the 4 threads of the head group (lane%4 == tc%4, consecutive lanes)
    float4 asv = *reinterpret_cast<const float4*>(att_src + tc * 4);
    float4 adv = *reinterpret_cast<const float4*>(att_dst + tc * 4);
#pragma unroll
    for (int i = 0; i < 4; i++) {
        float ps = acc[i][0] * asv.x + acc[i][1] * asv.y + acc[i][2] * asv.z + acc[i][3] * asv.w;
        float pd = acc[i][0] * adv.x + acc[i][1] * adv.y + acc[i][2] * adv.z + acc[i][3] * adv.w;
        ps += __shfl_xor_sync(0xffffffffu, ps, 1);
        ps += __shfl_xor_sync(0xffffffffu, ps, 2);
        pd += __shfl_xor_sync(0xffffffffu, pd, 1);
        pd += __shfl_xor_sync(0xffffffffu, pd, 2);
        int n = n0 + tn * 4 + i;
        if ((tc & 3) == 0 && n < N) {
            int head = tc >> 2;
            ((float*)g_asrc4)[n * 4 + head] = ps;
            ((float*)g_adst4)[n * 4 + head] = pd;
        }
    }
}

// ---------------- K7 (joined): per-edge exp(lrelu(logit)) + CSR permute ---
__global__ void k_edge(const int* __restrict__ ei, const float4* __restrict__ ea4, int E) {
    __shared__ float sv[64];
    if (threadIdx.x < 64) sv[threadIdx.x] = g_v[threadIdx.x];
    __syncthreads();
    int e = blockIdx.x * blockDim.x + threadIdx.x;
    if (e >= E) return;
    int src = ei[e], dst = ei[E + e];
    float a0 = 0.f, a1 = 0.f, a2 = 0.f, a3 = 0.f;
#pragma unroll
    for (int k = 0; k < 4; k++) {
        float4 q = __ldcs(ea4 + e * 4 + k);   // stream, evict-first
        const float* vp = sv + k * 16;
        a0 += q.x * vp[0] + q.y * vp[4] + q.z * vp[8]  + q.w * vp[12];
        a1 += q.x * vp[1] + q.y * vp[5] + q.z * vp[9]  + q.w * vp[13];
        a2 += q.x * vp[2] + q.y * vp[6] + q.z * vp[10] + q.w * vp[14];
        a3 += q.x * vp[3] + q.y * vp[7] + q.z * vp[11] + q.w * vp[15];
    }
    float4 as = g_asrc4[src];
    float4 ad = g_adst4[dst];
    Ex4 ex;
    ex.a = __floats2half2_rn(__expf(lrelu(as.x + ad.x + a0)),
                             __expf(lrelu(as.y + ad.y + a1)));
    ex.b = __floats2half2_rn(__expf(lrelu(as.z + ad.z + a2)),
                             __expf(lrelu(as.w + ad.w + a3)));
    int pos = atomicAdd(&g_cur[dst], 1);
    g_src_s[pos] = src;
    g_exs[pos] = ex;
}

// ---------------- K8: per-node register aggregation (fp16 gathers) --------
// one warp per node; lane owns channels {2*lane, 2*lane+1}, head = lane>>3
__global__ void k_agg(const float* __restrict__ bias, float* __restrict__ out, int N) {
    int n = (blockIdx.x * blockDim.x + threadIdx.x) >> 5;
    int lane = threadIdx.x & 31;
    if (n >= N) return;
    int off = g_off[n], deg = g_cnt[n];
    int h = lane >> 3;

    float acc0 = 0.f, acc1 = 0.f, dn = 0.f;

    int i = 0;
    for (; i + 4 <= deg; i += 4) {
        int s0 = __ldg(g_src_s + off + i);
        int s1 = __ldg(g_src_s + off + i + 1);
        int s2 = __ldg(g_src_s + off + i + 2);
        int s3 = __ldg(g_src_s + off + i + 3);
        Ex4 e0 = g_exs[off + i],     e1 = g_exs[off + i + 1];
        Ex4 e2 = g_exs[off + i + 2], e3 = g_exs[off + i + 3];
        __half2 q0 = __ldg(g_h2 + s0 * 32 + lane);
        __half2 q1 = __ldg(g_h2 + s1 * 32 + lane);
        __half2 q2 = __ldg(g_h2 + s2 * 32 + lane);
        __half2 q3 = __ldg(g_h2 + s3 * 32 + lane);
        __half2 hw0 = (h < 2) ? e0.a : e0.b;
        __half2 hw1 = (h < 2) ? e1.a : e1.b;
        __half2 hw2 = (h < 2) ? e2.a : e2.b;
        __half2 hw3 = (h < 2) ? e3.a : e3.b;
        float w0 = (h & 1) ? __high2float(hw0) : __low2float(hw0);
        float w1 = (h & 1) ? __high2float(hw1) : __low2float(hw1);
        float w2 = (h & 1) ? __high2float(hw2) : __low2float(hw2);
        float w3 = (h & 1) ? __high2float(hw3) : __low2float(hw3);
        float2 f0 = __half22float2(q0), f1 = __half22float2(q1);
        float2 f2 = __half22float2(q2), f3 = __half22float2(q3);
        acc0 += w0 * f0.x + w1 * f1.x + w2 * f2.x + w3 * f3.x;
        acc1 += w0 * f0.y + w1 * f1.y + w2 * f2.y + w3 * f3.y;
        dn   += w0 + w1 + w2 + w3;
    }
    for (; i < deg; i++) {
        int s0 = __ldg(g_src_s + off + i);
        Ex4 e0 = g_exs[off + i];
        __half2 q0 = __ldg(g_h2 + s0 * 32 + lane);
        __half2 hw0 = (h < 2) ? e0.a : e0.b;
        float w0 = (h & 1) ? __high2float(hw0) : __low2float(hw0);
        float2 f0 = __half22float2(q0);
        acc0 += w0 * f0.x;
        acc1 += w0 * f0.y;
        dn   += w0;
    }

    // self loop (fp32 h)
    float sl = ((const float*)g_asrc4)[n * 4 + h] + ((const float*)g_adst4)[n * 4 + h] + g_vsum[h];
    float es = __expf(lrelu(sl));
    const float* hn = (const float*)g_h4 + n * 64;
    float r = 1.f / (dn + es);
    float o0 = (acc0 + es * hn[2 * lane])     * r + __ldg(bias + 2 * lane);
    float o1 = (acc1 + es * hn[2 * lane + 1]) * r + __ldg(bias + 2 * lane + 1);
    reinterpret_cast<float2*>(out + n * 64)[lane] = make_float2(o0, o1);
}

// ---------------- launch ---------------------------------------------------
extern "C" void kernel_launch(void* const* d_in, const int* in_sizes, int n_in,
                              void* d_out, int out_size) {
    const float* x        = (const float*)d_in[0];
    const int*   ei       = (const int*)d_in[1];
    const float* ea       = (const float*)d_in[2];
    const float* W        = (const float*)d_in[3];
    const float* att_src  = (const float*)d_in[4];
    const float* att_dst  = (const float*)d_in[5];
    const float* W_edge   = (const float*)d_in[6];
    const float* att_edge = (const float*)d_in[7];
    const float* bias     = (const float*)d_in[8];
    float* out = (float*)d_out;

    int N = in_sizes[0] / 128;
    int E = in_sizes[1] / 2;
    int nscan = (N + SCAN_CHUNK - 1) / SCAN_CHUNK;

    const int gemm_smem = (8192 + 64 * 132) * 4;

    static cudaStream_t sB = nullptr;
    static cudaEvent_t evF = nullptr, evJ = nullptr;
    if (!sB) {
        cudaFuncSetAttribute(k_gemm, cudaFuncAttributeMaxDynamicSharedMemorySize, gemm_smem);
        cudaStreamCreateWithFlags(&sB, cudaStreamNonBlocking);
        cudaEventCreateWithFlags(&evF, cudaEventDisableTiming);
        cudaEventCreateWithFlags(&evJ, cudaEventDisableTiming);
    }

    cudaEventRecord(evF, 0);
    cudaStreamWaitEvent(sB, evF, 0);

    // chain B: CSR build
    k_prep<<<(N + 255) / 256, 256, 0, sB>>>(W_edge, att_edge, N);
    k_hist<<<(E + 2047) / 2048, 256, 0, sB>>>(ei, E);
    k_scan1<<<nscan, SCAN_CHUNK, 0, sB>>>(N);
    k_scan2<<<1, 256, 0, sB>>>(nscan);
    k_scan3<<<nscan, SCAN_CHUNK, 0, sB>>>(N);

    // chain A: gemm (+fused att dots)
    k_gemm<<<(N + 63) / 64, 256, gemm_smem>>>(x, W, att_src, att_dst, N);

    cudaEventRecord(evJ, sB);
    cudaStreamWaitEvent(0, evJ, 0);

    k_edge<<<(E + 255) / 256, 256>>>(ei, (const float4*)ea, E);
    k_agg<<<(N * 32 + 255) / 256, 256>>>(bias, out, N);
}